// round 11
// baseline (speedup 1.0000x reference)
#include <cuda_runtime.h>
#include <cuda_bf16.h>
#include <cstdint>

#define BATCH 4
#define NHEAD 8
#define S_LEN 2048
#define FDIM  1024
#define DHEAD 128
#define ZTOT  (BATCH*NHEAD)
#define NTOK  (BATCH*S_LEN)
#define QSZ   ((size_t)ZTOT*S_LEN*DHEAD)
#define WSZE  ((size_t)FDIM*FDIM)

// ---------------- scratch ----------------
static __device__ float g_sig[4];
static __device__ float g_v1[4][FDIM];
static __device__ float g_s1[4][FDIM];
static __device__ __align__(128) uint32_t g_xtf[(size_t)NTOK*FDIM];     // x tf32 (v proj)
static __device__ __align__(128) uint16_t g_xbh[(size_t)NTOK*FDIM];     // x bf16 hi
static __device__ __align__(128) uint16_t g_xbl[(size_t)NTOK*FDIM];     // x bf16 lo
static __device__ __align__(128) uint32_t g_wtf[2][WSZE];               // wv, wo tf32 (n-contig)
static __device__ __align__(128) uint16_t g_wth[2*WSZE];                // wq^T, wk^T bf16 hi [out][in]
static __device__ __align__(128) uint16_t g_wtl[2*WSZE];                // wq^T, wk^T bf16 lo
static __device__ __align__(128) uint16_t g_qkh[2*QSZ];                 // q,k bf16 hi [B,H,S,D]
static __device__ __align__(128) uint16_t g_qkl[2*QSZ];                 // q,k bf16 lo
static __device__ __align__(128) uint32_t g_vh[QSZ];                    // v tf32
static __device__ __align__(128) uint32_t g_ctxh[(size_t)NTOK*FDIM];    // ctx tf32
static __device__ __align__(128) float2 g_stats[(size_t)ZTOT*S_LEN*16];

// ---------------- helpers ----------------
__device__ __forceinline__ float warp_sum(float v){
    #pragma unroll
    for (int o=16;o;o>>=1) v += __shfl_xor_sync(0xffffffffu, v, o);
    return v;
}
__device__ __forceinline__ uint32_t f2tf(float x){
    uint32_t r; asm("cvt.rna.tf32.f32 %0, %1;" : "=r"(r) : "f"(x)); return r;
}
__device__ __forceinline__ uint16_t f2bf(float x){
    __nv_bfloat16 h = __float2bfloat16(x);
    return *reinterpret_cast<uint16_t*>(&h);
}
__device__ __forceinline__ float bf2f(uint16_t u){
    __nv_bfloat16 h; *reinterpret_cast<uint16_t*>(&h) = u;
    return __bfloat162float(h);
}
__device__ __forceinline__ void mma8(float* c, const uint32_t* a, const uint32_t* b){
    asm volatile(
        "mma.sync.aligned.m16n8k8.row.col.f32.tf32.tf32.f32 "
        "{%0,%1,%2,%3},{%4,%5,%6,%7},{%8,%9},{%0,%1,%2,%3};\n"
        : "+f"(c[0]), "+f"(c[1]), "+f"(c[2]), "+f"(c[3])
        : "r"(a[0]), "r"(a[1]), "r"(a[2]), "r"(a[3]), "r"(b[0]), "r"(b[1]));
}
__device__ __forceinline__ void mma16(float* c, const uint32_t* a, const uint32_t* b){
    asm volatile(
        "mma.sync.aligned.m16n8k16.row.col.f32.bf16.bf16.f32 "
        "{%0,%1,%2,%3},{%4,%5,%6,%7},{%8,%9},{%0,%1,%2,%3};\n"
        : "+f"(c[0]), "+f"(c[1]), "+f"(c[2]), "+f"(c[3])
        : "r"(a[0]), "r"(a[1]), "r"(a[2]), "r"(a[3]), "r"(b[0]), "r"(b[1]));
}
__device__ __forceinline__ void cp16(void* s, const void* g){
    uint32_t sa = (uint32_t)__cvta_generic_to_shared(s);
    asm volatile("cp.async.cg.shared.global [%0], [%1], 16;\n" :: "r"(sa), "l"(g));
}

// ---------------- merged conversions: x -> tf32+bf16hi/lo, wv/wo -> tf32 ----
__global__ void __launch_bounds__(256) k_conv(
    const float4* __restrict__ x, const float4* __restrict__ wv,
    const float4* __restrict__ wo,
    uint4* __restrict__ xtf, uint2* __restrict__ xbh, uint2* __restrict__ xbl,
    uint4* __restrict__ wtf)
{
    const int NXB = (NTOK*FDIM/4)/256;       // 8192
    const int NWB = (int)(WSZE/4)/256;       // 1024
    int b = blockIdx.x;
    if (b < NXB){
        size_t i = (size_t)b*256 + threadIdx.x;
        float4 v = x[i];
        xtf[i] = make_uint4(f2tf(v.x), f2tf(v.y), f2tf(v.z), f2tf(v.w));
        uint16_t h0=f2bf(v.x), h1=f2bf(v.y), h2=f2bf(v.z), h3=f2bf(v.w);
        xbh[i] = make_uint2((uint32_t)h0 | ((uint32_t)h1<<16), (uint32_t)h2 | ((uint32_t)h3<<16));
        uint16_t l0=f2bf(v.x-bf2f(h0)), l1=f2bf(v.y-bf2f(h1)),
                 l2=f2bf(v.z-bf2f(h2)), l3=f2bf(v.w-bf2f(h3));
        xbl[i] = make_uint2((uint32_t)l0 | ((uint32_t)l1<<16), (uint32_t)l2 | ((uint32_t)l3<<16));
    } else {
        int s   = (b - NXB) / NWB;
        size_t i = (size_t)((b - NXB) % NWB)*256 + threadIdx.x;
        const float4* src = s ? wo : wv;
        float4 v = src[i];
        wtf[(size_t)s*(WSZE/4) + i] = make_uint4(f2tf(v.x), f2tf(v.y), f2tf(v.z), f2tf(v.w));
    }
}
// wq, wk -> transposed bf16 hi/lo: Wt[n][k] = W[k][n]
__global__ void __launch_bounds__(256) k_transp(const float* __restrict__ w0,
    const float* __restrict__ w1, uint16_t* __restrict__ th, uint16_t* __restrict__ tl){
    __shared__ float t[32][33];
    int s = blockIdx.z;
    const float* W = s ? w1 : w0;
    uint16_t* Th = th + (size_t)s*WSZE;
    uint16_t* Tl = tl + (size_t)s*WSZE;
    int k0 = blockIdx.y*32, n0 = blockIdx.x*32;
    int r = threadIdx.x>>5, c = threadIdx.x&31;
    #pragma unroll
    for (int i=0;i<4;i++)
        t[r+8*i][c] = W[(size_t)(k0+r+8*i)*FDIM + n0 + c];
    __syncthreads();
    #pragma unroll
    for (int i=0;i<4;i++){
        float v = t[c][r+8*i];
        uint16_t hi = f2bf(v);
        size_t o = (size_t)(n0+r+8*i)*FDIM + k0 + c;
        Th[o] = hi;
        Tl[o] = f2bf(v - bf2f(hi));
    }
}

// ---------------- spectral norm (exact fp32) ----------------
__global__ void k_sigma_v(const float* w0,const float* w1,const float* w2,const float* w3,
                          const float* u0,const float* u1,const float* u2,const float* u3){
    const float* Wt[4]={w0,w1,w2,w3};
    const float* Ut[4]={u0,u1,u2,u3};
    int wi = blockIdx.y;
    const float* W = Wt[wi];
    const float* U = Ut[wi];
    int lane = threadIdx.x&31, warp = threadIdx.x>>5;
    int row = blockIdx.x*8 + warp;
    const float* r = W + (size_t)row*FDIM;
    float acc = 0.f;
    for (int j=lane;j<FDIM;j+=32) acc += U[j]*r[j];
    acc = warp_sum(acc);
    if (!lane) g_v1[wi][row] = acc;
}
__global__ void k_sigma_s(const float* w0,const float* w1,const float* w2,const float* w3){
    const float* Wt[4]={w0,w1,w2,w3};
    int wi = blockIdx.y;
    const float* W = Wt[wi];
    int o = blockIdx.x*256 + threadIdx.x;
    float acc = 0.f;
    for (int i=0;i<FDIM;i++) acc += g_v1[wi][i]*W[(size_t)i*FDIM+o];
    g_s1[wi][o] = acc;
}
__global__ void k_sigma_fin(){
    __shared__ float rv[8], rs[8];
    int wi = blockIdx.x, tid = threadIdx.x;
    float sv=0.f, ss=0.f;
    for (int i=tid;i<FDIM;i+=256){
        float a=g_v1[wi][i]; sv += a*a;
        float b=g_s1[wi][i]; ss += b*b;
    }
    sv = warp_sum(sv); ss = warp_sum(ss);
    if ((tid&31)==0){ rv[tid>>5]=sv; rs[tid>>5]=ss; }
    __syncthreads();
    if (tid==0){
        float a=0.f,b=0.f;
        for (int i=0;i<8;i++){ a+=rv[i]; b+=rs[i]; }
        g_sig[wi] = sqrtf(a/b);
    }
}

// ---------------- bf16x3 GEMM (fp32-class), C = A B^T, k-contig ----
// CTA 128x128, k-tile 32, 8 warps (2x4).
// EPI==0: QK logits (streaming store) + softmax stats. EPI==1: proj q/k.
template<int EPI>
__global__ void __launch_bounds__(256,2) gemm_bf3(
    const uint16_t* __restrict__ Ah0, const uint16_t* __restrict__ Al0,
    const uint16_t* __restrict__ Bh0, const uint16_t* __restrict__ Bl0,
    float* __restrict__ Dst, uint16_t* __restrict__ Dhi, uint16_t* __restrict__ Dlo,
    int K, int lda, int ldb,
    const float* __restrict__ sig, const float* __restrict__ b0p,
    const float* __restrict__ b1p)
{
    constexpr int RW  = 20;         // u32 words per 32-elem row (16 + 4 pad)
    constexpr int ARR = 128*RW;
    constexpr int STRIDE = 4*ARR;   // Ahi,Alo,Bhi,Blo
    extern __shared__ uint32_t sm[];

    const int tid = threadIdx.x;
    const int lane = tid & 31;
    const int warp = tid >> 5;
    const int wm = warp >> 2;
    const int wn = warp & 3;
    const int rl = lane >> 2;
    const int cl = lane & 3;
    const int z = blockIdx.z;
    const int mblk = blockIdx.y * 128;
    const int nblk = blockIdx.x * 128;

    const uint16_t* Agh = Ah0;
    const uint16_t* Agl = Al0;
    const uint16_t* Bgh = Bh0;
    const uint16_t* Bgl = Bl0;
    if (EPI==0){
        size_t zo = (size_t)z*S_LEN*DHEAD;
        Agh += zo; Agl += zo; Bgh += zo; Bgl += zo;
    } else {
        Bgh += (size_t)z*WSZE; Bgl += (size_t)z*WSZE;
    }
    Agh += (size_t)mblk*lda; Agl += (size_t)mblk*lda;
    Bgh += (size_t)nblk*ldb; Bgl += (size_t)nblk*ldb;

    float acc[4][4][4];
    #pragma unroll
    for (int i=0;i<4;i++)
        #pragma unroll
        for (int j=0;j<4;j++)
            #pragma unroll
            for (int r=0;r<4;r++) acc[i][j][r]=0.f;

    const int nkt = K >> 5;

    auto issue = [&](int buf){
        uint32_t* Ah = sm + buf*STRIDE;
        uint32_t* Al = Ah + ARR;
        uint32_t* Bh = Ah + 2*ARR;
        uint32_t* Bl = Ah + 3*ARR;
        #pragma unroll
        for (int i=0;i<2;i++){
            int idx = tid + i*256;
            int row = idx>>2, ch = idx&3;
            int off = row*RW + ch*4;
            size_t ga = (size_t)row*lda + ch*8;
            size_t gb = (size_t)row*ldb + ch*8;
            cp16(&Ah[off], Agh + ga);
            cp16(&Al[off], Agl + ga);
            cp16(&Bh[off], Bgh + gb);
            cp16(&Bl[off], Bgl + gb);
        }
        asm volatile("cp.async.commit_group;\n" ::: "memory");
    };

    issue(0);

    for (int kt=0; kt<nkt; kt++){
        asm volatile("cp.async.wait_group 0;\n" ::: "memory");
        __syncthreads();
        if (kt+1 < nkt){
            Agh += 32; Agl += 32; Bgh += 32; Bgl += 32;
            issue((kt+1)&1);
        }
        const uint32_t* Ah = sm + (kt&1)*STRIDE;
        const uint32_t* Al = Ah + ARR;
        const uint32_t* Bh = Ah + 2*ARR;
        const uint32_t* Bl = Ah + 3*ARR;

        #pragma unroll
        for (int ks=0; ks<2; ks++){
            const int kb = ks*8;
            uint32_t ah[4][4], al[4][4];
            #pragma unroll
            for (int mt=0; mt<4; mt++){
                int base = (wm*64 + mt*16 + rl)*RW + kb + cl;
                ah[mt][0]=Ah[base];       ah[mt][1]=Ah[base+8*RW];
                ah[mt][2]=Ah[base+4];     ah[mt][3]=Ah[base+8*RW+4];
                al[mt][0]=Al[base];       al[mt][1]=Al[base+8*RW];
                al[mt][2]=Al[base+4];     al[mt][3]=Al[base+8*RW+4];
            }
            #pragma unroll
            for (int nt=0; nt<4; nt++){
                int bb = (wn*32 + nt*8 + rl)*RW + kb + cl;
                uint32_t bh[2], bl[2];
                bh[0]=Bh[bb]; bh[1]=Bh[bb+4];
                bl[0]=Bl[bb]; bl[1]=Bl[bb+4];
                #pragma unroll
                for (int mt=0; mt<4; mt++){
                    mma16(acc[mt][nt], ah[mt], bh);
                    mma16(acc[mt][nt], ah[mt], bl);
                    mma16(acc[mt][nt], al[mt], bh);
                }
            }
        }
    }

    // ---- epilogue ----
    float sg = 1.f;
    if (EPI==1) sg = sig[z];
    const float* bb = (EPI==1) ? (z ? b1p : b0p) : b0p;
    #pragma unroll
    for (int mt=0; mt<4; mt++){
        #pragma unroll
        for (int nt=0; nt<4; nt++){
            int row0 = mblk + wm*64 + mt*16 + rl;
            int col  = nblk + wn*32 + nt*8 + 2*cl;
            #pragma unroll
            for (int h2=0; h2<2; h2++){
                int row = row0 + h2*8;
                float v0 = acc[mt][nt][h2*2+0];
                float v1 = acc[mt][nt][h2*2+1];
                if (EPI==0){
                    __stcs(reinterpret_cast<float2*>(Dst + (size_t)z*S_LEN*S_LEN + (size_t)row*S_LEN + col),
                           make_float2(v0, v1));
                } else {
                    float o0 = v0*sg + bb[col];
                    float o1 = v1*sg + bb[col+1];
                    int b = row >> 11, s = row & (S_LEN-1);
                    int h = col >> 7, d = col & (DHEAD-1);
                    size_t o = (size_t)z*QSZ + (((size_t)(b*NHEAD+h))*S_LEN + s)*DHEAD + d;
                    uint16_t h0 = f2bf(o0), h1 = f2bf(o1);
                    *reinterpret_cast<uint32_t*>(Dhi + o) = (uint32_t)h0 | ((uint32_t)h1<<16);
                    uint16_t l0 = f2bf(o0 - bf2f(h0)), l1 = f2bf(o1 - bf2f(h1));
                    *reinterpret_cast<uint32_t*>(Dlo + o) = (uint32_t)l0 | ((uint32_t)l1<<16);
                }
            }
        }
    }

    if constexpr (EPI==0){
        __shared__ float sMx[4][128];
        __shared__ float sSm[4][128];
        #pragma unroll
        for (int mt=0; mt<4; mt++){
            #pragma unroll
            for (int h2=0; h2<2; h2++){
                float m = acc[mt][0][h2*2];
                #pragma unroll
                for (int nt=0; nt<4; nt++){
                    m = fmaxf(m, acc[mt][nt][h2*2+0]);
                    m = fmaxf(m, acc[mt][nt][h2*2+1]);
                }
                float s = 0.f;
                #pragma unroll
                for (int nt=0; nt<4; nt++){
                    s += __expf(acc[mt][nt][h2*2+0] - m);
                    s += __expf(acc[mt][nt][h2*2+1] - m);
                }
                #pragma unroll
                for (int off=1; off<4; off<<=1){
                    float om = __shfl_xor_sync(0xffffffffu, m, off);
                    float os = __shfl_xor_sync(0xffffffffu, s, off);
                    float nm = fmaxf(m, om);
                    s = s*__expf(m-nm) + os*__expf(om-nm);
                    m = nm;
                }
                if (cl==0){
                    int rloc = wm*64 + mt*16 + h2*8 + rl;
                    sMx[wn][rloc] = m;
                    sSm[wn][rloc] = s;
                }
            }
        }
        __syncthreads();
        if (tid < 128){
            float M = sMx[0][tid], S = sSm[0][tid];
            #pragma unroll
            for (int w=1; w<4; w++){
                float m2 = sMx[w][tid], s2 = sSm[w][tid];
                float nm = fmaxf(M, m2);
                S = S*__expf(M-nm) + s2*__expf(m2-nm);
                M = nm;
            }
            g_stats[((size_t)z*S_LEN + mblk + tid)*16 + blockIdx.x] = make_float2(M, S);
        }
    }
}

// ---------------- tf32 x1 GEMM (v proj / out proj), B [K,N] n-contig ----------
template<int EPI>
__global__ void __launch_bounds__(256,2) gemm_tf(
    const uint32_t* __restrict__ A0, const uint32_t* __restrict__ B0,
    float* __restrict__ Dst, uint32_t* __restrict__ Dh,
    int K, int lda, int ldb,
    const float* __restrict__ sig, const float* __restrict__ b0p,
    const float* __restrict__ x0, const float* __restrict__ gammap)
{
    constexpr int ASZ = 128*36;
    constexpr int BSZ = 32*136;
    constexpr int STRIDE = ASZ + BSZ;
    extern __shared__ uint32_t sm[];

    const int tid = threadIdx.x;
    const int lane = tid & 31;
    const int warp = tid >> 5;
    const int wm = warp >> 2;
    const int wn = warp & 3;
    const int rl = lane >> 2;
    const int cl = lane & 3;
    const int mblk = blockIdx.y * 128;
    const int nblk = blockIdx.x * 128;

    const uint32_t* Ag = A0 + (size_t)mblk*lda;
    const uint32_t* Bg = B0 + nblk;

    float acc[4][4][4];
    #pragma unroll
    for (int i=0;i<4;i++)
        #pragma unroll
        for (int j=0;j<4;j++)
            #pragma unroll
            for (int r=0;r<4;r++) acc[i][j][r]=0.f;

    const int nkt = K >> 5;

    auto issue = [&](int buf){
        uint32_t* Ab = sm + buf*STRIDE;
        uint32_t* Bb = Ab + ASZ;
        #pragma unroll
        for (int i=0;i<4;i++){
            int idx = tid + i*256;
            cp16(&Ab[(idx>>3)*36 + ((idx&7)<<2)], Ag + (size_t)(idx>>3)*lda + ((idx&7)<<2));
        }
        #pragma unroll
        for (int i=0;i<4;i++){
            int idx = tid + i*256;
            cp16(&Bb[(idx>>5)*136 + ((idx&31)<<2)], Bg + (size_t)(idx>>5)*ldb + ((idx&31)<<2));
        }
        asm volatile("cp.async.commit_group;\n" ::: "memory");
    };

    issue(0);

    for (int kt=0; kt<nkt; kt++){
        asm volatile("cp.async.wait_group 0;\n" ::: "memory");
        __syncthreads();
        if (kt+1 < nkt){
            Ag += 32;
            Bg += (size_t)32*ldb;
            issue((kt+1)&1);
        }
        const uint32_t* Ac = sm + (kt&1)*STRIDE;
        const uint32_t* Bc = Ac + ASZ;

        #pragma unroll
        for (int ks=0; ks<4; ks++){
            const int kb = ks*8;
            uint32_t ah[4][4], bh[4][2];
            #pragma unroll
            for (int mt=0; mt<4; mt++){
                int base = (wm*64 + mt*16 + rl)*36 + kb + cl;
                ah[mt][0]=Ac[base];     ah[mt][1]=Ac[base+288];
                ah[mt][2]=Ac[base+4];   ah[mt][3]=Ac[base+292];
            }
            #pragma unroll
            for (int nt=0; nt<4; nt++){
                int base = (kb + cl)*136 + wn*32 + nt*8 + rl;
                bh[nt][0]=Bc[base]; bh[nt][1]=Bc[base+544];
            }
            #pragma unroll
            for (int mt=0; mt<4; mt++)
                #pragma unroll
                for (int nt=0; nt<4; nt++)
                    mma8(acc[mt][nt], ah[mt], bh[nt]);
        }
    }

    float sg = (EPI==1) ? sig[0] : sig[3];
    float gm = (EPI==3) ? *gammap : 1.f;
    #pragma unroll
    for (int mt=0; mt<4; mt++){
        #pragma unroll
        for (int nt=0; nt<4; nt++){
            int row0 = mblk + wm*64 + mt*16 + rl;
            int col  = nblk + wn*32 + nt*8 + 2*cl;
            #pragma unroll
            for (int h2=0; h2<2; h2++){
                int row = row0 + h2*8;
                float v0 = acc[mt][nt][h2*2+0];
                float v1 = acc[mt][nt][h2*2+1];
                if (EPI==1){
                    float o0 = v0*sg + b0p[col];
                    float o1 = v1*sg + b0p[col+1];
                    int b = row >> 11, s = row & (S_LEN-1);
                    int h = col >> 7, d = col & (DHEAD-1);
                    size_t o = (((size_t)(b*NHEAD+h))*S_LEN + s)*DHEAD + d;
                    *reinterpret_cast<uint2*>(Dh + o) = make_uint2(f2tf(o0), f2tf(o1));
                } else {
                    size_t idx = (size_t)row*FDIM + col;
                    float2 xv = __ldcs(reinterpret_cast<const float2*>(x0 + idx));
                    float o0 = xv.x + (v0*sg + b0p[col])*gm;
                    float o1 = xv.y + (v1*sg + b0p[col+1])*gm;
                    *reinterpret_cast<float2*>(Dst + idx) = make_float2(o0, o1);
                }
            }
        }
    }
}

// ---------------- AV GEMM: stats merge + softmax-normalize + writeback ------
__global__ void __launch_bounds__(256,2) gemm_av(
    float* __restrict__ attn,
    const uint32_t* __restrict__ Bv,
    uint32_t* __restrict__ Dst)
{
    extern __shared__ uint32_t avsm[];
    uint32_t* Atf = avsm;            // 2 x 128*36
    uint32_t* Btf = avsm + 2*4608;   // 3 x 32*136
    __shared__ float sM[128], sI[128];

    const int tid = threadIdx.x;
    const int lane = tid & 31;
    const int warp = tid >> 5;
    const int wm = warp >> 2;
    const int wn = warp & 3;
    const int rl = lane >> 2;
    const int cl = lane & 3;
    const int z = blockIdx.z;
    const int mblk = blockIdx.y * 128;
    const int nkt = S_LEN >> 5;

    float*          Ag = attn + (size_t)z*S_LEN*S_LEN + (size_t)mblk*S_LEN;
    const uint32_t* Bg = Bv   + (size_t)z*S_LEN*DHEAD;

    int crow[4], ckk[4];
    #pragma unroll
    for (int i=0;i<4;i++){ int idx = tid + i*256; crow[i]=idx>>3; ckk[i]=(idx&7)<<2; }

    auto issueB = [&](int t){
        int bb = t % 3;
        #pragma unroll
        for (int i=0;i<4;i++){
            int idx = tid + i*256;
            cp16(&Btf[bb*4352 + (idx>>5)*136 + ((idx&31)<<2)],
                 Bg + ((size_t)t*32 + (idx>>5))*DHEAD + ((idx&31)<<2));
        }
        asm volatile("cp.async.commit_group;\n" ::: "memory");
    };

    float4 ra[2][4];
    auto ldgA = [&](int t){
        #pragma unroll
        for (int i=0;i<4;i++)
            ra[t&1][i] = __ldcs(reinterpret_cast<const float4*>(Ag + (size_t)crow[i]*S_LEN + t*32 + ckk[i]));
    };
    auto xform = [&](int t){
        int ab = t & 1;
        #pragma unroll
        for (int i=0;i<4;i++){
            float M = sM[crow[i]], inv = sI[crow[i]];
            float4 v = ra[ab][i];
            float4 p;
            p.x = __expf(v.x - M)*inv;
            p.y = __expf(v.y - M)*inv;
            p.z = __expf(v.z - M)*inv;
            p.w = __expf(v.w - M)*inv;
            *reinterpret_cast<uint4*>(&Atf[ab*4608 + crow[i]*36 + ckk[i]]) =
                make_uint4(f2tf(p.x), f2tf(p.y), f2tf(p.z), f2tf(p.w));
            __stcs(reinterpret_cast<float4*>(Ag + (size_t)crow[i]*S_LEN + t*32 + ckk[i]), p);
        }
    };

    float acc[4][4][4];
    #pragma unroll
    for (int i=0;i<4;i++)
        #pragma unroll
        for (int j=0;j<4;j++)
            #pragma unroll
            for (int r=0;r<4;r++) acc[i][j][r]=0.f;

    issueB(0);
    ldgA(0);
    issueB(1);
    ldgA(1);

    // per-row softmax stat merge (folded k_merge): each thread owns one row
    if (tid < 128){
        const float2* st = g_stats + ((size_t)z*S_LEN + mblk + tid)*16;
        float2 p0 = st[0];
        float M = p0.x, S = p0.y;
        #pragma unroll
        for (int i=1;i<16;i++){
            float2 p = st[i];
            float nm = fmaxf(M, p.x);
            S = S*__expf(M-nm) + p.y*__expf(p.x-nm);
            M = nm;
        }
        sM[tid] = M;
        sI[tid] = 1.f/S;
    }

    __syncthreads();
    xform(0);

    for (int kt=0; kt<nkt; kt++){
        asm volatile("cp.async.wait_group 0;\n" ::: "memory");
        __syncthreads();
        if (kt+2 < nkt){
            issueB(kt+2);
            ldgA(kt+2);
        }
        if (kt+1 < nkt) xform(kt+1);

        const uint32_t* Ah = Atf + (kt&1)*4608;
        const uint32_t* Bh = Btf + (kt%3)*4352;
        #pragma unroll
        for (int ks=0; ks<4; ks++){
            const int kb = ks*8;
            uint32_t ah[4][4], bh[4][2];
            #pragma unroll
            for (int mt=0; mt<4; mt++){
                int base = (wm*64 + mt*16 + rl)*36 + kb + cl;
                ah[mt][0]=Ah[base];     ah[mt][1]=Ah[base+288];
                ah[mt][2]=Ah[base+4];   ah[mt][3]=Ah[base+292];
            }
            #pragma unroll
            for (int nt=0; nt<4; nt++){
                int base = (kb + cl)*136 + wn*32 + nt*8 + rl;
                bh[nt][0]=Bh[base]; bh[nt][1]=Bh[base+544];
            }
            #pragma unroll
            for (int mt=0; mt<4; mt++)
                #pragma unroll
                for (int nt=0; nt<4; nt++)
                    mma8(acc[mt][nt], ah[mt], bh[nt]);
        }
    }

    const int b = z >> 3, h = z & 7;
    #pragma unroll
    for (int mt=0; mt<4; mt++){
        #pragma unroll
        for (int nt=0; nt<4; nt++){
            int row0 = mblk + wm*64 + mt*16 + rl;
            int col  = wn*32 + nt*8 + 2*cl;
            #pragma unroll
            for (int h2=0; h2<2; h2++){
                int row = row0 + h2*8;
                *reinterpret_cast<uint2*>(Dst + ((size_t)b*S_LEN + row)*FDIM + h*DHEAD + col)
                    = make_uint2(f2tf(acc[mt][nt][h2*2+0]), f2tf(acc[mt][nt][h2*2+1]));
            }
        }
    }
}

// ---------------- launch ----------------
extern "C" void kernel_launch(void* const* d_in, const int* in_sizes, int n_in,
                              void* d_out, int out_size)
{
    (void)in_sizes; (void)n_in; (void)out_size;
    const float* x  = (const float*)d_in[0];
    const float* wq = (const float*)d_in[1];
    const float* bq = (const float*)d_in[2];
    const float* uq = (const float*)d_in[3];
    const float* wk = (const float*)d_in[4];
    const float* bk = (const float*)d_in[5];
    const float* uk = (const float*)d_in[6];
    const float* wv = (const float*)d_in[7];
    const float* bv = (const float*)d_in[8];
    const float* uv = (const float*)d_in[9];
    const float* wo = (const float*)d_in[10];
    const float* bo = (const float*)d_in[11];
    const float* uo = (const float*)d_in[12];
    const float* gm = (const float*)d_in[13];

    float* out  = (float*)d_out;
    float* attn = out + (size_t)NTOK*FDIM;

    uint32_t *pxtf,*pwtf,*pvh,*pctxh;
    uint16_t *pxbh,*pxbl,*pwth,*pwtl,*pqkh,*pqkl;
    float *psig;
    cudaGetSymbolAddress((void**)&pxtf,  g_xtf);
    cudaGetSymbolAddress((void**)&pxbh,  g_xbh);
    cudaGetSymbolAddress((void**)&pxbl,  g_xbl);
    cudaGetSymbolAddress((void**)&pwtf,  g_wtf);
    cudaGetSymbolAddress((void**)&pwth,  g_wth);
    cudaGetSymbolAddress((void**)&pwtl,  g_wtl);
    cudaGetSymbolAddress((void**)&pqkh,  g_qkh);
    cudaGetSymbolAddress((void**)&pqkl,  g_qkl);
    cudaGetSymbolAddress((void**)&pvh,   g_vh);
    cudaGetSymbolAddress((void**)&pctxh, g_ctxh);
    cudaGetSymbolAddress((void**)&psig,  g_sig);

    cudaFuncSetAttribute(gemm_bf3<0>, cudaFuncAttributeMaxDynamicSharedMemorySize, 81920);
    cudaFuncSetAttribute(gemm_bf3<1>, cudaFuncAttributeMaxDynamicSharedMemorySize, 81920);
    cudaFuncSetAttribute(gemm_tf<1>,  cudaFuncAttributeMaxDynamicSharedMemorySize, 71680);
    cudaFuncSetAttribute(gemm_tf<3>,  cudaFuncAttributeMaxDynamicSharedMemorySize, 71680);
    cudaFuncSetAttribute(gemm_av,     cudaFuncAttributeMaxDynamicSharedMemorySize, 89088);

    // conversions + spectral norms (launch indices 0-4)
    k_conv<<<8192+2*1024,256>>>((const float4*)x,(const float4*)wv,(const float4*)wo,
                                (uint4*)pxtf,(uint2*)pxbh,(uint2*)pxbl,(uint4*)pwtf);
    k_transp<<<dim3(32,32,2),256>>>(wq, wk, pwth, pwtl);
    k_sigma_v<<<dim3(128,4),256>>>(wq,wk,wv,wo, uq,uk,uv,uo);
    k_sigma_s<<<dim3(4,4),256>>>(wq,wk,wv,wo);
    k_sigma_fin<<<4,256>>>();

    // q,k projections (bf16x3, z=2)  — launch index 5: ncu captures this
    gemm_bf3<1><<<dim3(8,64,2),256,81920>>>(pxbh, pxbl, pwth, pwtl,
        nullptr, pqkh, pqkl, FDIM, FDIM, FDIM, psig, bq, bk);

    // v projection (tf32 x1)
    gemm_tf<1><<<dim3(8,64,1),256,71680>>>(pxtf, pwtf, nullptr, pvh,
        FDIM, FDIM, FDIM, psig+2, bv, nullptr, nullptr);

    // logits = q k^T (bf16x3) + stats, streaming logits store
    gemm_bf3<0><<<dim3(16,16,32),256,81920>>>(pqkh, pqkl, pqkh+QSZ, pqkl+QSZ,
        attn, nullptr, nullptr, DHEAD, DHEAD, DHEAD, nullptr, nullptr, nullptr);

    // ctx = softmax(logits) @ v; stats merged inline; probs in place (.cs)
    gemm_av<<<dim3(1,16,32),256,89088>>>(attn, pvh, pctxh);

    // out = x + (ctx @ wo + bo) * gamma
    gemm_tf<3><<<dim3(8,64,1),256,71680>>>(pctxh, pwtf+WSZE, out, nullptr,
        FDIM, FDIM, FDIM, psig, bo, x, gm);
}

// round 12
// speedup vs baseline: 1.0352x; 1.0352x over previous
#include <cuda_runtime.h>
#include <cuda_bf16.h>
#include <cstdint>

#define BATCH 4
#define NHEAD 8
#define S_LEN 2048
#define FDIM  1024
#define DHEAD 128
#define ZTOT  (BATCH*NHEAD)
#define NTOK  (BATCH*S_LEN)
#define QSZ   ((size_t)ZTOT*S_LEN*DHEAD)
#define WSZE  ((size_t)FDIM*FDIM)

// ---------------- scratch ----------------
static __device__ float g_sig[4];
static __device__ float g_v1[4][FDIM];
static __device__ float g_s1p[32][4][FDIM];                             // partial sums
static __device__ __align__(128) uint32_t g_xtf[(size_t)NTOK*FDIM];     // x tf32 (v proj)
static __device__ __align__(128) uint16_t g_xbh[(size_t)NTOK*FDIM];     // x bf16 hi
static __device__ __align__(128) uint16_t g_xbl[(size_t)NTOK*FDIM];     // x bf16 lo
static __device__ __align__(128) uint32_t g_wtf[2][WSZE];               // wv, wo tf32 (n-contig)
static __device__ __align__(128) uint16_t g_wth[2*WSZE];                // wq^T, wk^T bf16 hi [out][in]
static __device__ __align__(128) uint16_t g_wtl[2*WSZE];                // wq^T, wk^T bf16 lo
static __device__ __align__(128) uint16_t g_qkh[2*QSZ];                 // q,k bf16 hi [B,H,S,D]
static __device__ __align__(128) uint16_t g_qkl[2*QSZ];                 // q,k bf16 lo
static __device__ __align__(128) uint32_t g_vh[QSZ];                    // v tf32
static __device__ __align__(128) uint32_t g_ctxh[(size_t)NTOK*FDIM];    // ctx tf32
static __device__ __align__(128) float2 g_stats[(size_t)ZTOT*S_LEN*16];

// ---------------- helpers ----------------
__device__ __forceinline__ float warp_sum(float v){
    #pragma unroll
    for (int o=16;o;o>>=1) v += __shfl_xor_sync(0xffffffffu, v, o);
    return v;
}
__device__ __forceinline__ uint32_t f2tf(float x){
    uint32_t r; asm("cvt.rna.tf32.f32 %0, %1;" : "=r"(r) : "f"(x)); return r;
}
__device__ __forceinline__ uint16_t f2bf(float x){
    __nv_bfloat16 h = __float2bfloat16(x);
    return *reinterpret_cast<uint16_t*>(&h);
}
__device__ __forceinline__ float bf2f(uint16_t u){
    __nv_bfloat16 h; *reinterpret_cast<uint16_t*>(&h) = u;
    return __bfloat162float(h);
}
__device__ __forceinline__ void mma8(float* c, const uint32_t* a, const uint32_t* b){
    asm volatile(
        "mma.sync.aligned.m16n8k8.row.col.f32.tf32.tf32.f32 "
        "{%0,%1,%2,%3},{%4,%5,%6,%7},{%8,%9},{%0,%1,%2,%3};\n"
        : "+f"(c[0]), "+f"(c[1]), "+f"(c[2]), "+f"(c[3])
        : "r"(a[0]), "r"(a[1]), "r"(a[2]), "r"(a[3]), "r"(b[0]), "r"(b[1]));
}
__device__ __forceinline__ void mma16(float* c, const uint32_t* a, const uint32_t* b){
    asm volatile(
        "mma.sync.aligned.m16n8k16.row.col.f32.bf16.bf16.f32 "
        "{%0,%1,%2,%3},{%4,%5,%6,%7},{%8,%9},{%0,%1,%2,%3};\n"
        : "+f"(c[0]), "+f"(c[1]), "+f"(c[2]), "+f"(c[3])
        : "r"(a[0]), "r"(a[1]), "r"(a[2]), "r"(a[3]), "r"(b[0]), "r"(b[1]));
}
__device__ __forceinline__ void cp16(void* s, const void* g){
    uint32_t sa = (uint32_t)__cvta_generic_to_shared(s);
    asm volatile("cp.async.cg.shared.global [%0], [%1], 16;\n" :: "r"(sa), "l"(g));
}

// ---------------- merged conversions: x -> tf32+bf16hi/lo, wv/wo -> tf32 ----
__global__ void __launch_bounds__(256) k_conv(
    const float4* __restrict__ x, const float4* __restrict__ wv,
    const float4* __restrict__ wo,
    uint4* __restrict__ xtf, uint2* __restrict__ xbh, uint2* __restrict__ xbl,
    uint4* __restrict__ wtf)
{
    const int NXB = (NTOK*FDIM/4)/256;       // 8192
    const int NWB = (int)(WSZE/4)/256;       // 1024
    int b = blockIdx.x;
    if (b < NXB){
        size_t i = (size_t)b*256 + threadIdx.x;
        float4 v = x[i];
        xtf[i] = make_uint4(f2tf(v.x), f2tf(v.y), f2tf(v.z), f2tf(v.w));
        uint16_t h0=f2bf(v.x), h1=f2bf(v.y), h2=f2bf(v.z), h3=f2bf(v.w);
        xbh[i] = make_uint2((uint32_t)h0 | ((uint32_t)h1<<16), (uint32_t)h2 | ((uint32_t)h3<<16));
        uint16_t l0=f2bf(v.x-bf2f(h0)), l1=f2bf(v.y-bf2f(h1)),
                 l2=f2bf(v.z-bf2f(h2)), l3=f2bf(v.w-bf2f(h3));
        xbl[i] = make_uint2((uint32_t)l0 | ((uint32_t)l1<<16), (uint32_t)l2 | ((uint32_t)l3<<16));
    } else {
        int s   = (b - NXB) / NWB;
        size_t i = (size_t)((b - NXB) % NWB)*256 + threadIdx.x;
        const float4* src = s ? wo : wv;
        float4 v = src[i];
        wtf[(size_t)s*(WSZE/4) + i] = make_uint4(f2tf(v.x), f2tf(v.y), f2tf(v.z), f2tf(v.w));
    }
}
// wq, wk -> transposed bf16 hi/lo: Wt[n][k] = W[k][n]
__global__ void __launch_bounds__(256) k_transp(const float* __restrict__ w0,
    const float* __restrict__ w1, uint16_t* __restrict__ th, uint16_t* __restrict__ tl){
    __shared__ float t[32][33];
    int s = blockIdx.z;
    const float* W = s ? w1 : w0;
    uint16_t* Th = th + (size_t)s*WSZE;
    uint16_t* Tl = tl + (size_t)s*WSZE;
    int k0 = blockIdx.y*32, n0 = blockIdx.x*32;
    int r = threadIdx.x>>5, c = threadIdx.x&31;
    #pragma unroll
    for (int i=0;i<4;i++)
        t[r+8*i][c] = W[(size_t)(k0+r+8*i)*FDIM + n0 + c];
    __syncthreads();
    #pragma unroll
    for (int i=0;i<4;i++){
        float v = t[c][r+8*i];
        uint16_t hi = f2bf(v);
        size_t o = (size_t)(n0+r+8*i)*FDIM + k0 + c;
        Th[o] = hi;
        Tl[o] = f2bf(v - bf2f(hi));
    }
}

// ---------------- spectral norm (exact fp32) ----------------
__global__ void k_sigma_v(const float* w0,const float* w1,const float* w2,const float* w3,
                          const float* u0,const float* u1,const float* u2,const float* u3){
    const float* Wt[4]={w0,w1,w2,w3};
    const float* Ut[4]={u0,u1,u2,u3};
    int wi = blockIdx.y;
    const float* W = Wt[wi];
    const float* U = Ut[wi];
    int lane = threadIdx.x&31, warp = threadIdx.x>>5;
    int row = blockIdx.x*8 + warp;
    const float* r = W + (size_t)row*FDIM;
    float acc = 0.f;
    for (int j=lane;j<FDIM;j+=32) acc += U[j]*r[j];
    acc = warp_sum(acc);
    if (!lane) g_v1[wi][row] = acc;
}
// s[o] = sum_i v1[i]*W[i][o], parallelized over 32 k-slices (two-stage, no atomics)
__global__ void __launch_bounds__(256) k_sigma_s(
    const float* w0,const float* w1,const float* w2,const float* w3){
    const float* Wt[4]={w0,w1,w2,w3};
    int wi = blockIdx.z;
    int ks = blockIdx.y;                       // 0..31
    int o  = blockIdx.x*256 + threadIdx.x;
    const float* W = Wt[wi];
    float acc = 0.f;
    #pragma unroll
    for (int j=0;j<32;j++){
        int i = ks*32 + j;
        acc += g_v1[wi][i]*W[(size_t)i*FDIM + o];
    }
    g_s1p[ks][wi][o] = acc;
}
__global__ void k_sigma_fin(){
    __shared__ float rv[8], rs[8];
    int wi = blockIdx.x, tid = threadIdx.x;
    float sv=0.f, ss=0.f;
    for (int i=tid;i<FDIM;i+=256){
        float a=g_v1[wi][i]; sv += a*a;
        float s=0.f;
        #pragma unroll
        for (int p=0;p<32;p++) s += g_s1p[p][wi][i];
        ss += s*s;
    }
    sv = warp_sum(sv); ss = warp_sum(ss);
    if ((tid&31)==0){ rv[tid>>5]=sv; rs[tid>>5]=ss; }
    __syncthreads();
    if (tid==0){
        float a=0.f,b=0.f;
        for (int i=0;i<8;i++){ a+=rv[i]; b+=rs[i]; }
        g_sig[wi] = sqrtf(a/b);
    }
}

// ---------------- bf16x3 GEMM (fp32-class), C = A B^T, k-contig ----
// CTA 128x128, k-tile 32, 8 warps (2x4).
// EPI==0: QK logits + softmax stats. EPI==1: proj q/k (bf16 hi/lo out).
template<int EPI>
__global__ void __launch_bounds__(256,2) gemm_bf3(
    const uint16_t* __restrict__ Ah0, const uint16_t* __restrict__ Al0,
    const uint16_t* __restrict__ Bh0, const uint16_t* __restrict__ Bl0,
    float* __restrict__ Dst, uint16_t* __restrict__ Dhi, uint16_t* __restrict__ Dlo,
    int K, int lda, int ldb,
    const float* __restrict__ sig, const float* __restrict__ b0p,
    const float* __restrict__ b1p)
{
    constexpr int RW  = 20;         // u32 words per 32-elem row (16 + 4 pad)
    constexpr int ARR = 128*RW;
    constexpr int STRIDE = 4*ARR;   // Ahi,Alo,Bhi,Blo
    extern __shared__ uint32_t sm[];

    const int tid = threadIdx.x;
    const int lane = tid & 31;
    const int warp = tid >> 5;
    const int wm = warp >> 2;
    const int wn = warp & 3;
    const int rl = lane >> 2;
    const int cl = lane & 3;
    const int z = blockIdx.z;
    const int mblk = blockIdx.y * 128;
    const int nblk = blockIdx.x * 128;

    const uint16_t* Agh = Ah0;
    const uint16_t* Agl = Al0;
    const uint16_t* Bgh = Bh0;
    const uint16_t* Bgl = Bl0;
    if (EPI==0){
        size_t zo = (size_t)z*S_LEN*DHEAD;
        Agh += zo; Agl += zo; Bgh += zo; Bgl += zo;
    } else {
        Bgh += (size_t)z*WSZE; Bgl += (size_t)z*WSZE;
    }
    Agh += (size_t)mblk*lda; Agl += (size_t)mblk*lda;
    Bgh += (size_t)nblk*ldb; Bgl += (size_t)nblk*ldb;

    float acc[4][4][4];
    #pragma unroll
    for (int i=0;i<4;i++)
        #pragma unroll
        for (int j=0;j<4;j++)
            #pragma unroll
            for (int r=0;r<4;r++) acc[i][j][r]=0.f;

    const int nkt = K >> 5;

    auto issue = [&](int buf){
        uint32_t* Ah = sm + buf*STRIDE;
        uint32_t* Al = Ah + ARR;
        uint32_t* Bh = Ah + 2*ARR;
        uint32_t* Bl = Ah + 3*ARR;
        #pragma unroll
        for (int i=0;i<2;i++){
            int idx = tid + i*256;
            int row = idx>>2, ch = idx&3;
            int off = row*RW + ch*4;
            size_t ga = (size_t)row*lda + ch*8;
            size_t gb = (size_t)row*ldb + ch*8;
            cp16(&Ah[off], Agh + ga);
            cp16(&Al[off], Agl + ga);
            cp16(&Bh[off], Bgh + gb);
            cp16(&Bl[off], Bgl + gb);
        }
        asm volatile("cp.async.commit_group;\n" ::: "memory");
    };

    issue(0);

    for (int kt=0; kt<nkt; kt++){
        asm volatile("cp.async.wait_group 0;\n" ::: "memory");
        __syncthreads();
        if (kt+1 < nkt){
            Agh += 32; Agl += 32; Bgh += 32; Bgl += 32;
            issue((kt+1)&1);
        }
        const uint32_t* Ah = sm + (kt&1)*STRIDE;
        const uint32_t* Al = Ah + ARR;
        const uint32_t* Bh = Ah + 2*ARR;
        const uint32_t* Bl = Ah + 3*ARR;

        #pragma unroll
        for (int ks=0; ks<2; ks++){
            const int kb = ks*8;
            uint32_t ah[4][4], al[4][4];
            #pragma unroll
            for (int mt=0; mt<4; mt++){
                int base = (wm*64 + mt*16 + rl)*RW + kb + cl;
                ah[mt][0]=Ah[base];       ah[mt][1]=Ah[base+8*RW];
                ah[mt][2]=Ah[base+4];     ah[mt][3]=Ah[base+8*RW+4];
                al[mt][0]=Al[base];       al[mt][1]=Al[base+8*RW];
                al[mt][2]=Al[base+4];     al[mt][3]=Al[base+8*RW+4];
            }
            #pragma unroll
            for (int nt=0; nt<4; nt++){
                int bb = (wn*32 + nt*8 + rl)*RW + kb + cl;
                uint32_t bh[2], bl[2];
                bh[0]=Bh[bb]; bh[1]=Bh[bb+4];
                bl[0]=Bl[bb]; bl[1]=Bl[bb+4];
                #pragma unroll
                for (int mt=0; mt<4; mt++){
                    mma16(acc[mt][nt], ah[mt], bh);
                    mma16(acc[mt][nt], ah[mt], bl);
                    mma16(acc[mt][nt], al[mt], bh);
                }
            }
        }
    }

    // ---- epilogue ----
    float sg = 1.f;
    if (EPI==1) sg = sig[z];
    const float* bb = (EPI==1) ? (z ? b1p : b0p) : b0p;
    #pragma unroll
    for (int mt=0; mt<4; mt++){
        #pragma unroll
        for (int nt=0; nt<4; nt++){
            int row0 = mblk + wm*64 + mt*16 + rl;
            int col  = nblk + wn*32 + nt*8 + 2*cl;
            #pragma unroll
            for (int h2=0; h2<2; h2++){
                int row = row0 + h2*8;
                float v0 = acc[mt][nt][h2*2+0];
                float v1 = acc[mt][nt][h2*2+1];
                if (EPI==0){
                    *reinterpret_cast<float2*>(Dst + (size_t)z*S_LEN*S_LEN + (size_t)row*S_LEN + col)
                        = make_float2(v0, v1);
                } else {
                    float o0 = v0*sg + bb[col];
                    float o1 = v1*sg + bb[col+1];
                    int b = row >> 11, s = row & (S_LEN-1);
                    int h = col >> 7, d = col & (DHEAD-1);
                    size_t o = (size_t)z*QSZ + (((size_t)(b*NHEAD+h))*S_LEN + s)*DHEAD + d;
                    uint16_t h0 = f2bf(o0), h1 = f2bf(o1);
                    *reinterpret_cast<uint32_t*>(Dhi + o) = (uint32_t)h0 | ((uint32_t)h1<<16);
                    uint16_t l0 = f2bf(o0 - bf2f(h0)), l1 = f2bf(o1 - bf2f(h1));
                    *reinterpret_cast<uint32_t*>(Dlo + o) = (uint32_t)l0 | ((uint32_t)l1<<16);
                }
            }
        }
    }

    if constexpr (EPI==0){
        __shared__ float sMx[4][128];
        __shared__ float sSm[4][128];
        #pragma unroll
        for (int mt=0; mt<4; mt++){
            #pragma unroll
            for (int h2=0; h2<2; h2++){
                float m = acc[mt][0][h2*2];
                #pragma unroll
                for (int nt=0; nt<4; nt++){
                    m = fmaxf(m, acc[mt][nt][h2*2+0]);
                    m = fmaxf(m, acc[mt][nt][h2*2+1]);
                }
                float s = 0.f;
                #pragma unroll
                for (int nt=0; nt<4; nt++){
                    s += __expf(acc[mt][nt][h2*2+0] - m);
                    s += __expf(acc[mt][nt][h2*2+1] - m);
                }
                #pragma unroll
                for (int off=1; off<4; off<<=1){
                    float om = __shfl_xor_sync(0xffffffffu, m, off);
                    float os = __shfl_xor_sync(0xffffffffu, s, off);
                    float nm = fmaxf(m, om);
                    s = s*__expf(m-nm) + os*__expf(om-nm);
                    m = nm;
                }
                if (cl==0){
                    int rloc = wm*64 + mt*16 + h2*8 + rl;
                    sMx[wn][rloc] = m;
                    sSm[wn][rloc] = s;
                }
            }
        }
        __syncthreads();
        if (tid < 128){
            float M = sMx[0][tid], S = sSm[0][tid];
            #pragma unroll
            for (int w=1; w<4; w++){
                float m2 = sMx[w][tid], s2 = sSm[w][tid];
                float nm = fmaxf(M, m2);
                S = S*__expf(M-nm) + s2*__expf(m2-nm);
                M = nm;
            }
            g_stats[((size_t)z*S_LEN + mblk + tid)*16 + blockIdx.x] = make_float2(M, S);
        }
    }
}

// ---------------- tf32 x1 GEMM (v proj / out proj), B [K,N] n-contig ----------
template<int EPI>
__global__ void __launch_bounds__(256,2) gemm_tf(
    const uint32_t* __restrict__ A0, const uint32_t* __restrict__ B0,
    float* __restrict__ Dst, uint32_t* __restrict__ Dh,
    int K, int lda, int ldb,
    const float* __restrict__ sig, const float* __restrict__ b0p,
    const float* __restrict__ x0, const float* __restrict__ gammap)
{
    constexpr int ASZ = 128*36;
    constexpr int BSZ = 32*136;
    constexpr int STRIDE = ASZ + BSZ;
    extern __shared__ uint32_t sm[];

    const int tid = threadIdx.x;
    const int lane = tid & 31;
    const int warp = tid >> 5;
    const int wm = warp >> 2;
    const int wn = warp & 3;
    const int rl = lane >> 2;
    const int cl = lane & 3;
    const int mblk = blockIdx.y * 128;
    const int nblk = blockIdx.x * 128;

    const uint32_t* Ag = A0 + (size_t)mblk*lda;
    const uint32_t* Bg = B0 + nblk;

    float acc[4][4][4];
    #pragma unroll
    for (int i=0;i<4;i++)
        #pragma unroll
        for (int j=0;j<4;j++)
            #pragma unroll
            for (int r=0;r<4;r++) acc[i][j][r]=0.f;

    const int nkt = K >> 5;

    auto issue = [&](int buf){
        uint32_t* Ab = sm + buf*STRIDE;
        uint32_t* Bb = Ab + ASZ;
        #pragma unroll
        for (int i=0;i<4;i++){
            int idx = tid + i*256;
            cp16(&Ab[(idx>>3)*36 + ((idx&7)<<2)], Ag + (size_t)(idx>>3)*lda + ((idx&7)<<2));
        }
        #pragma unroll
        for (int i=0;i<4;i++){
            int idx = tid + i*256;
            cp16(&Bb[(idx>>5)*136 + ((idx&31)<<2)], Bg + (size_t)(idx>>5)*ldb + ((idx&31)<<2));
        }
        asm volatile("cp.async.commit_group;\n" ::: "memory");
    };

    issue(0);

    for (int kt=0; kt<nkt; kt++){
        asm volatile("cp.async.wait_group 0;\n" ::: "memory");
        __syncthreads();
        if (kt+1 < nkt){
            Ag += 32;
            Bg += (size_t)32*ldb;
            issue((kt+1)&1);
        }
        const uint32_t* Ac = sm + (kt&1)*STRIDE;
        const uint32_t* Bc = Ac + ASZ;

        #pragma unroll
        for (int ks=0; ks<4; ks++){
            const int kb = ks*8;
            uint32_t ah[4][4], bh[4][2];
            #pragma unroll
            for (int mt=0; mt<4; mt++){
                int base = (wm*64 + mt*16 + rl)*36 + kb + cl;
                ah[mt][0]=Ac[base];     ah[mt][1]=Ac[base+288];
                ah[mt][2]=Ac[base+4];   ah[mt][3]=Ac[base+292];
            }
            #pragma unroll
            for (int nt=0; nt<4; nt++){
                int base = (kb + cl)*136 + wn*32 + nt*8 + rl;
                bh[nt][0]=Bc[base]; bh[nt][1]=Bc[base+544];
            }
            #pragma unroll
            for (int mt=0; mt<4; mt++)
                #pragma unroll
                for (int nt=0; nt<4; nt++)
                    mma8(acc[mt][nt], ah[mt], bh[nt]);
        }
    }

    float sg = (EPI==1) ? sig[0] : sig[3];
    float gm = (EPI==3) ? *gammap : 1.f;
    #pragma unroll
    for (int mt=0; mt<4; mt++){
        #pragma unroll
        for (int nt=0; nt<4; nt++){
            int row0 = mblk + wm*64 + mt*16 + rl;
            int col  = nblk + wn*32 + nt*8 + 2*cl;
            #pragma unroll
            for (int h2=0; h2<2; h2++){
                int row = row0 + h2*8;
                float v0 = acc[mt][nt][h2*2+0];
                float v1 = acc[mt][nt][h2*2+1];
                if (EPI==1){
                    float o0 = v0*sg + b0p[col];
                    float o1 = v1*sg + b0p[col+1];
                    int b = row >> 11, s = row & (S_LEN-1);
                    int h = col >> 7, d = col & (DHEAD-1);
                    size_t o = (((size_t)(b*NHEAD+h))*S_LEN + s)*DHEAD + d;
                    *reinterpret_cast<uint2*>(Dh + o) = make_uint2(f2tf(o0), f2tf(o1));
                } else {
                    size_t idx = (size_t)row*FDIM + col;
                    float o0 = x0[idx]   + (v0*sg + b0p[col])*gm;
                    float o1 = x0[idx+1] + (v1*sg + b0p[col+1])*gm;
                    *reinterpret_cast<float2*>(Dst + idx) = make_float2(o0, o1);
                }
            }
        }
    }
}

// ---------------- AV GEMM: stats merge + softmax-normalize + writeback ------
__global__ void __launch_bounds__(256,2) gemm_av(
    float* __restrict__ attn,
    const uint32_t* __restrict__ Bv,
    uint32_t* __restrict__ Dst)
{
    extern __shared__ uint32_t avsm[];
    uint32_t* Atf = avsm;            // 2 x 128*36
    uint32_t* Btf = avsm + 2*4608;   // 3 x 32*136
    __shared__ float sM[128], sI[128];

    const int tid = threadIdx.x;
    const int lane = tid & 31;
    const int warp = tid >> 5;
    const int wm = warp >> 2;
    const int wn = warp & 3;
    const int rl = lane >> 2;
    const int cl = lane & 3;
    const int z = blockIdx.z;
    const int mblk = blockIdx.y * 128;
    const int nkt = S_LEN >> 5;

    float*          Ag = attn + (size_t)z*S_LEN*S_LEN + (size_t)mblk*S_LEN;
    const uint32_t* Bg = Bv   + (size_t)z*S_LEN*DHEAD;

    int crow[4], ckk[4];
    #pragma unroll
    for (int i=0;i<4;i++){ int idx = tid + i*256; crow[i]=idx>>3; ckk[i]=(idx&7)<<2; }

    auto issueB = [&](int t){
        int bb = t % 3;
        #pragma unroll
        for (int i=0;i<4;i++){
            int idx = tid + i*256;
            cp16(&Btf[bb*4352 + (idx>>5)*136 + ((idx&31)<<2)],
                 Bg + ((size_t)t*32 + (idx>>5))*DHEAD + ((idx&31)<<2));
        }
        asm volatile("cp.async.commit_group;\n" ::: "memory");
    };

    float4 ra[2][4];
    auto ldgA = [&](int t){
        #pragma unroll
        for (int i=0;i<4;i++)
            ra[t&1][i] = *reinterpret_cast<const float4*>(Ag + (size_t)crow[i]*S_LEN + t*32 + ckk[i]);
    };
    auto xform = [&](int t){
        int ab = t & 1;
        #pragma unroll
        for (int i=0;i<4;i++){
            float M = sM[crow[i]], inv = sI[crow[i]];
            float4 v = ra[ab][i];
            float4 p;
            p.x = __expf(v.x - M)*inv;
            p.y = __expf(v.y - M)*inv;
            p.z = __expf(v.z - M)*inv;
            p.w = __expf(v.w - M)*inv;
            *reinterpret_cast<uint4*>(&Atf[ab*4608 + crow[i]*36 + ckk[i]]) =
                make_uint4(f2tf(p.x), f2tf(p.y), f2tf(p.z), f2tf(p.w));
            *reinterpret_cast<float4*>(Ag + (size_t)crow[i]*S_LEN + t*32 + ckk[i]) = p;
        }
    };

    float acc[4][4][4];
    #pragma unroll
    for (int i=0;i<4;i++)
        #pragma unroll
        for (int j=0;j<4;j++)
            #pragma unroll
            for (int r=0;r<4;r++) acc[i][j][r]=0.f;

    issueB(0);
    ldgA(0);
    issueB(1);
    ldgA(1);

    // per-row softmax stat merge (folded k_merge): each thread owns one row
    if (tid < 128){
        const float2* st = g_stats + ((size_t)z*S_LEN + mblk + tid)*16;
        float2 p0 = st[0];
        float M = p0.x, S = p0.y;
        #pragma unroll
        for (int i=1;i<16;i++){
            float2 p = st[i];
            float nm = fmaxf(M, p.x);
            S = S*__expf(M-nm) + p.y*__expf(p.x-nm);
            M = nm;
        }
        sM[tid] = M;
        sI[tid] = 1.f/S;
    }

    __syncthreads();
    xform(0);

    for (int kt=0; kt<nkt; kt++){
        asm volatile("cp.async.wait_group 0;\n" ::: "memory");
        __syncthreads();
        if (kt+2 < nkt){
            issueB(kt+2);
            ldgA(kt+2);
        }
        if (kt+1 < nkt) xform(kt+1);

        const uint32_t* Ah = Atf + (kt&1)*4608;
        const uint32_t* Bh = Btf + (kt%3)*4352;
        #pragma unroll
        for (int ks=0; ks<4; ks++){
            const int kb = ks*8;
            uint32_t ah[4][4], bh[4][2];
            #pragma unroll
            for (int mt=0; mt<4; mt++){
                int base = (wm*64 + mt*16 + rl)*36 + kb + cl;
                ah[mt][0]=Ah[base];     ah[mt][1]=Ah[base+288];
                ah[mt][2]=Ah[base+4];   ah[mt][3]=Ah[base+292];
            }
            #pragma unroll
            for (int nt=0; nt<4; nt++){
                int base = (kb + cl)*136 + wn*32 + nt*8 + rl;
                bh[nt][0]=Bh[base]; bh[nt][1]=Bh[base+544];
            }
            #pragma unroll
            for (int mt=0; mt<4; mt++)
                #pragma unroll
                for (int nt=0; nt<4; nt++)
                    mma8(acc[mt][nt], ah[mt], bh[nt]);
        }
    }

    const int b = z >> 3, h = z & 7;
    #pragma unroll
    for (int mt=0; mt<4; mt++){
        #pragma unroll
        for (int nt=0; nt<4; nt++){
            int row0 = mblk + wm*64 + mt*16 + rl;
            int col  = wn*32 + nt*8 + 2*cl;
            #pragma unroll
            for (int h2=0; h2<2; h2++){
                int row = row0 + h2*8;
                *reinterpret_cast<uint2*>(Dst + ((size_t)b*S_LEN + row)*FDIM + h*DHEAD + col)
                    = make_uint2(f2tf(acc[mt][nt][h2*2+0]), f2tf(acc[mt][nt][h2*2+1]));
            }
        }
    }
}

// ---------------- launch ----------------
extern "C" void kernel_launch(void* const* d_in, const int* in_sizes, int n_in,
                              void* d_out, int out_size)
{
    (void)in_sizes; (void)n_in; (void)out_size;
    const float* x  = (const float*)d_in[0];
    const float* wq = (const float*)d_in[1];
    const float* bq = (const float*)d_in[2];
    const float* uq = (const float*)d_in[3];
    const float* wk = (const float*)d_in[4];
    const float* bk = (const float*)d_in[5];
    const float* uk = (const float*)d_in[6];
    const float* wv = (const float*)d_in[7];
    const float* bv = (const float*)d_in[8];
    const float* uv = (const float*)d_in[9];
    const float* wo = (const float*)d_in[10];
    const float* bo = (const float*)d_in[11];
    const float* uo = (const float*)d_in[12];
    const float* gm = (const float*)d_in[13];

    float* out  = (float*)d_out;
    float* attn = out + (size_t)NTOK*FDIM;

    uint32_t *pxtf,*pwtf,*pvh,*pctxh;
    uint16_t *pxbh,*pxbl,*pwth,*pwtl,*pqkh,*pqkl;
    float *psig;
    cudaGetSymbolAddress((void**)&pxtf,  g_xtf);
    cudaGetSymbolAddress((void**)&pxbh,  g_xbh);
    cudaGetSymbolAddress((void**)&pxbl,  g_xbl);
    cudaGetSymbolAddress((void**)&pwtf,  g_wtf);
    cudaGetSymbolAddress((void**)&pwth,  g_wth);
    cudaGetSymbolAddress((void**)&pwtl,  g_wtl);
    cudaGetSymbolAddress((void**)&pqkh,  g_qkh);
    cudaGetSymbolAddress((void**)&pqkl,  g_qkl);
    cudaGetSymbolAddress((void**)&pvh,   g_vh);
    cudaGetSymbolAddress((void**)&pctxh, g_ctxh);
    cudaGetSymbolAddress((void**)&psig,  g_sig);

    cudaFuncSetAttribute(gemm_bf3<0>, cudaFuncAttributeMaxDynamicSharedMemorySize, 81920);
    cudaFuncSetAttribute(gemm_bf3<1>, cudaFuncAttributeMaxDynamicSharedMemorySize, 81920);
    cudaFuncSetAttribute(gemm_tf<1>,  cudaFuncAttributeMaxDynamicSharedMemorySize, 71680);
    cudaFuncSetAttribute(gemm_tf<3>,  cudaFuncAttributeMaxDynamicSharedMemorySize, 71680);
    cudaFuncSetAttribute(gemm_av,     cudaFuncAttributeMaxDynamicSharedMemorySize, 89088);

    // conversions + spectral norms (launch indices 0-4)
    k_conv<<<8192+2*1024,256>>>((const float4*)x,(const float4*)wv,(const float4*)wo,
                                (uint4*)pxtf,(uint2*)pxbh,(uint2*)pxbl,(uint4*)pwtf);
    k_transp<<<dim3(32,32,2),256>>>(wq, wk, pwth, pwtl);
    k_sigma_v<<<dim3(128,4),256>>>(wq,wk,wv,wo, uq,uk,uv,uo);
    k_sigma_s<<<dim3(4,32,4),256>>>(wq,wk,wv,wo);
    k_sigma_fin<<<4,256>>>();

    // q,k projections (bf16x3, z=2)  — launch index 5: ncu captures this
    gemm_bf3<1><<<dim3(8,64,2),256,81920>>>(pxbh, pxbl, pwth, pwtl,
        nullptr, pqkh, pqkl, FDIM, FDIM, FDIM, psig, bq, bk);

    // v projection (tf32 x1)
    gemm_tf<1><<<dim3(8,64,1),256,71680>>>(pxtf, pwtf, nullptr, pvh,
        FDIM, FDIM, FDIM, psig+2, bv, nullptr, nullptr);

    // logits = q k^T (bf16x3) + stats
    gemm_bf3<0><<<dim3(16,16,32),256,81920>>>(pqkh, pqkl, pqkh+QSZ, pqkl+QSZ,
        attn, nullptr, nullptr, DHEAD, DHEAD, DHEAD, nullptr, nullptr, nullptr);

    // ctx = softmax(logits) @ v; stats merged inline; probs in place
    gemm_av<<<dim3(1,16,32),256,89088>>>(attn, pvh, pctxh);

    // out = x + (ctx @ wo + bo) * gamma
    gemm_tf<3><<<dim3(8,64,1),256,71680>>>(pctxh, pwtf+WSZE, out, nullptr,
        FDIM, FDIM, FDIM, psig, bo, x, gm);
}